// round 1
// baseline (speedup 1.0000x reference)
#include <cuda_runtime.h>
#include <math.h>

#define B_   8
#define LQ_  2048
#define LK_  2048
#define HID_ 1024

// ---------------------------------------------------------------------------
// Kernel 1: P[b,q,k] = exp( (Q[b,q,:] . K[b,k,:]) / 32 * mask[b,q,k] )
// Tiled SGEMM "NT" (both operands K-major / inner-dim contiguous).
// BM = BN = 128, BK = 8, 256 threads, 8x8 microtile per thread.
// P written UNNORMALIZED into the attn output region; k2 normalizes.
// ---------------------------------------------------------------------------
__global__ __launch_bounds__(256)
void k1_qk_exp(const float* __restrict__ Q, const float* __restrict__ Kf,
               const float* __restrict__ mask, float* __restrict__ P)
{
    __shared__ float As[8][128];
    __shared__ float Bs[8][128];

    const int b  = blockIdx.z;
    const int m0 = blockIdx.y * 128;
    const int n0 = blockIdx.x * 128;

    const float* Qb = Q  + (size_t)b * LQ_ * HID_;
    const float* Kb = Kf + (size_t)b * LK_ * HID_;

    const int tid = threadIdx.x;
    const int tx  = tid & 15;          // 0..15  -> column group (8 cols)
    const int ty  = tid >> 4;          // 0..15  -> row group    (8 rows)

    // loader mapping: 128 rows x 8 cols tile, one float4 per thread
    const int lm = tid >> 1;           // 0..127
    const int lk = (tid & 1) * 4;      // 0 or 4

    float acc[8][8];
#pragma unroll
    for (int i = 0; i < 8; i++)
#pragma unroll
        for (int j = 0; j < 8; j++) acc[i][j] = 0.0f;

    for (int kk = 0; kk < HID_; kk += 8) {
        float4 a  = *(const float4*)(Qb + (size_t)(m0 + lm) * HID_ + kk + lk);
        float4 bv = *(const float4*)(Kb + (size_t)(n0 + lm) * HID_ + kk + lk);
        As[lk + 0][lm] = a.x;  As[lk + 1][lm] = a.y;
        As[lk + 2][lm] = a.z;  As[lk + 3][lm] = a.w;
        Bs[lk + 0][lm] = bv.x; Bs[lk + 1][lm] = bv.y;
        Bs[lk + 2][lm] = bv.z; Bs[lk + 3][lm] = bv.w;
        __syncthreads();

#pragma unroll
        for (int k = 0; k < 8; k++) {
            float4 a0 = *(const float4*)&As[k][ty * 8];
            float4 a1 = *(const float4*)&As[k][ty * 8 + 4];
            float4 b0 = *(const float4*)&Bs[k][tx * 8];
            float4 b1 = *(const float4*)&Bs[k][tx * 8 + 4];
            float ar[8] = {a0.x, a0.y, a0.z, a0.w, a1.x, a1.y, a1.z, a1.w};
            float br[8] = {b0.x, b0.y, b0.z, b0.w, b1.x, b1.y, b1.z, b1.w};
#pragma unroll
            for (int i = 0; i < 8; i++)
#pragma unroll
                for (int j = 0; j < 8; j++)
                    acc[i][j] = fmaf(ar[i], br[j], acc[i][j]);
        }
        __syncthreads();
    }

    // Epilogue: scale by 1/32, multiply by mask, exp, store (2x float4 per row)
    const float s = 0.03125f;  // 1/sqrt(1024)
#pragma unroll
    for (int i = 0; i < 8; i++) {
        const int q = m0 + ty * 8 + i;
        const size_t rbase = ((size_t)b * LQ_ + q) * LK_ + n0 + tx * 8;
        float4 m0v = *(const float4*)(mask + rbase);
        float4 m1v = *(const float4*)(mask + rbase + 4);
        float4 o0, o1;
        o0.x = expf(acc[i][0] * s * m0v.x);
        o0.y = expf(acc[i][1] * s * m0v.y);
        o0.z = expf(acc[i][2] * s * m0v.z);
        o0.w = expf(acc[i][3] * s * m0v.w);
        o1.x = expf(acc[i][4] * s * m1v.x);
        o1.y = expf(acc[i][5] * s * m1v.y);
        o1.z = expf(acc[i][6] * s * m1v.z);
        o1.w = expf(acc[i][7] * s * m1v.w);
        *(float4*)(P + rbase)     = o0;
        *(float4*)(P + rbase + 4) = o1;
    }
}

// ---------------------------------------------------------------------------
// Kernel 2: per-row normalization. One block per (b,q) row of 2048 entries.
// ---------------------------------------------------------------------------
__global__ __launch_bounds__(256)
void k2_norm(float* __restrict__ P)
{
    __shared__ float red[256];
    float* prow = P + (size_t)blockIdx.x * LK_;
    const int tid = threadIdx.x;

    float4 v0 = ((const float4*)prow)[tid];
    float4 v1 = ((const float4*)prow)[tid + 256];
    float s = v0.x + v0.y + v0.z + v0.w + v1.x + v1.y + v1.z + v1.w;
    red[tid] = s;
    __syncthreads();
#pragma unroll
    for (int off = 128; off > 0; off >>= 1) {
        if (tid < off) red[tid] += red[tid + off];
        __syncthreads();
    }
    const float inv = 1.0f / red[0];
    v0.x *= inv; v0.y *= inv; v0.z *= inv; v0.w *= inv;
    v1.x *= inv; v1.y *= inv; v1.z *= inv; v1.w *= inv;
    ((float4*)prow)[tid]       = v0;
    ((float4*)prow)[tid + 256] = v1;
}

// ---------------------------------------------------------------------------
// Kernel 3: context[b,q,d] = sum_k attn[b,q,k] * K[b,k,d]
// Tiled SGEMM "NN": A (attn) is k-contiguous, B (K) is d-contiguous.
// Same 128x128x8 tiling, 8x8 microtile.
// ---------------------------------------------------------------------------
__global__ __launch_bounds__(256)
void k3_av(const float* __restrict__ A, const float* __restrict__ Kf,
           float* __restrict__ C)
{
    __shared__ float As[8][128];
    __shared__ float Bs[8][128];

    const int b  = blockIdx.z;
    const int m0 = blockIdx.y * 128;
    const int n0 = blockIdx.x * 128;

    const float* Ab = A  + (size_t)b * LQ_ * LK_;
    const float* Kb = Kf + (size_t)b * LK_ * HID_;

    const int tid = threadIdx.x;
    const int tx  = tid & 15;
    const int ty  = tid >> 4;

    // A loader: 128 rows x 8 cols (k), transpose into As
    const int lm = tid >> 1;
    const int lk = (tid & 1) * 4;
    // B loader: 8 rows (k) x 128 cols (d), direct
    const int br = tid >> 5;           // 0..7
    const int bc = (tid & 31) * 4;     // 0..124

    float acc[8][8];
#pragma unroll
    for (int i = 0; i < 8; i++)
#pragma unroll
        for (int j = 0; j < 8; j++) acc[i][j] = 0.0f;

    for (int kk = 0; kk < LK_; kk += 8) {
        float4 a = *(const float4*)(Ab + (size_t)(m0 + lm) * LK_ + kk + lk);
        As[lk + 0][lm] = a.x; As[lk + 1][lm] = a.y;
        As[lk + 2][lm] = a.z; As[lk + 3][lm] = a.w;
        float4 bv = *(const float4*)(Kb + (size_t)(kk + br) * HID_ + n0 + bc);
        *(float4*)&Bs[br][bc] = bv;
        __syncthreads();

#pragma unroll
        for (int k = 0; k < 8; k++) {
            float4 a0 = *(const float4*)&As[k][ty * 8];
            float4 a1 = *(const float4*)&As[k][ty * 8 + 4];
            float4 b0 = *(const float4*)&Bs[k][tx * 8];
            float4 b1 = *(const float4*)&Bs[k][tx * 8 + 4];
            float ar[8] = {a0.x, a0.y, a0.z, a0.w, a1.x, a1.y, a1.z, a1.w};
            float br2[8] = {b0.x, b0.y, b0.z, b0.w, b1.x, b1.y, b1.z, b1.w};
#pragma unroll
            for (int i = 0; i < 8; i++)
#pragma unroll
                for (int j = 0; j < 8; j++)
                    acc[i][j] = fmaf(ar[i], br2[j], acc[i][j]);
        }
        __syncthreads();
    }

#pragma unroll
    for (int i = 0; i < 8; i++) {
        const int q = m0 + ty * 8 + i;
        const size_t rbase = ((size_t)b * LQ_ + q) * HID_ + n0 + tx * 8;
        float4 o0 = make_float4(acc[i][0], acc[i][1], acc[i][2], acc[i][3]);
        float4 o1 = make_float4(acc[i][4], acc[i][5], acc[i][6], acc[i][7]);
        *(float4*)(C + rbase)     = o0;
        *(float4*)(C + rbase + 4) = o1;
    }
}

// ---------------------------------------------------------------------------
extern "C" void kernel_launch(void* const* d_in, const int* in_sizes, int n_in,
                              void* d_out, int out_size)
{
    const float* Q    = (const float*)d_in[0];
    const float* Kf   = (const float*)d_in[1];
    const float* mask = (const float*)d_in[2];

    float* ctx  = (float*)d_out;                              // [B, LQ, HID]
    float* attn = ctx + (size_t)B_ * LQ_ * HID_;              // [B, LQ, LK]

    dim3 g1(LK_ / 128, LQ_ / 128, B_);
    k1_qk_exp<<<g1, 256>>>(Q, Kf, mask, attn);

    k2_norm<<<B_ * LQ_, 256>>>(attn);

    dim3 g3(HID_ / 128, LQ_ / 128, B_);
    k3_av<<<g3, 256>>>(attn, Kf, ctx);
}

// round 2
// speedup vs baseline: 3.1136x; 3.1136x over previous
#include <cuda_runtime.h>
#include <math.h>

#define B_   8
#define LQ_  2048
#define LK_  2048
#define HID_ 1024

// ---------------------------------------------------------------------------
// tf32 warp MMA helpers (m16n8k8, row.col, f32 accum)
// ---------------------------------------------------------------------------
__device__ __forceinline__ unsigned f2tf(float x) {
    unsigned u;
    asm("cvt.rna.tf32.f32 %0, %1;" : "=r"(u) : "f"(x));
    return u;
}

__device__ __forceinline__ void mma_tf32(float* d, const unsigned* a, const unsigned* b) {
    asm volatile(
        "mma.sync.aligned.m16n8k8.row.col.f32.tf32.tf32.f32 "
        "{%0,%1,%2,%3}, {%4,%5,%6,%7}, {%8,%9}, {%0,%1,%2,%3};\n"
        : "+f"(d[0]), "+f"(d[1]), "+f"(d[2]), "+f"(d[3])
        : "r"(a[0]), "r"(a[1]), "r"(a[2]), "r"(a[3]),
          "r"(b[0]), "r"(b[1]));
}

// smem strides (floats) chosen for conflict-free fragment reads:
//  k-major tiles  [row][k], stride 20:  bank = (20*row + k) % 32, distinct over
//    the (8 rows x 4 k) quad pattern of a0/b0 fragment loads.
//  n-major tile   [k][n],  stride 136:  bank = (8*k + n) % 32, distinct.
#define SK 20
#define SN 136

// ---------------------------------------------------------------------------
// Kernel 1: P = exp( (Q.K^T / 32) * mask )   (unnormalized; k2 normalizes)
// BM=BN=128, BK=16, 256 threads = 8 warps (2x4), warp tile 64x32.
// ---------------------------------------------------------------------------
__global__ __launch_bounds__(256, 2)
void k1_qk_exp(const float* __restrict__ Q, const float* __restrict__ Kf,
               const float* __restrict__ mask, float* __restrict__ P)
{
    __shared__ unsigned sA[2][128 * SK];
    __shared__ unsigned sB[2][128 * SK];

    const int b  = blockIdx.z;
    const int m0 = blockIdx.y * 128;
    const int n0 = blockIdx.x * 128;

    const float* Qb = Q  + (size_t)b * LQ_ * HID_;
    const float* Kb = Kf + (size_t)b * LK_ * HID_;

    const int tid  = threadIdx.x;
    const int wid  = tid >> 5;
    const int lane = tid & 31;
    const int qid  = lane >> 2;   // 0..7
    const int rid  = lane & 3;    // 0..3
    const int wm   = (wid >> 2) * 64;   // warp row offset
    const int wn   = (wid & 3) * 32;    // warp col offset

    // loader: idx -> (row 0..127, kq in {0,4,8,12}), two float4 per thread
    const int r0l = tid >> 2;
    const int kql = (tid & 3) << 2;

    float acc[4][4][4];
#pragma unroll
    for (int i = 0; i < 4; i++)
#pragma unroll
        for (int j = 0; j < 4; j++)
#pragma unroll
            for (int c = 0; c < 4; c++) acc[i][j][c] = 0.0f;

    // prologue: load k-chunk 0 into buffer 0
    {
        float4 a0 = *(const float4*)(Qb + (size_t)(m0 + r0l) * HID_ + kql);
        float4 a1 = *(const float4*)(Qb + (size_t)(m0 + r0l + 64) * HID_ + kql);
        float4 b0 = *(const float4*)(Kb + (size_t)(n0 + r0l) * HID_ + kql);
        float4 b1 = *(const float4*)(Kb + (size_t)(n0 + r0l + 64) * HID_ + kql);
        *(uint4*)&sA[0][r0l * SK + kql] =
            make_uint4(f2tf(a0.x), f2tf(a0.y), f2tf(a0.z), f2tf(a0.w));
        *(uint4*)&sA[0][(r0l + 64) * SK + kql] =
            make_uint4(f2tf(a1.x), f2tf(a1.y), f2tf(a1.z), f2tf(a1.w));
        *(uint4*)&sB[0][r0l * SK + kql] =
            make_uint4(f2tf(b0.x), f2tf(b0.y), f2tf(b0.z), f2tf(b0.w));
        *(uint4*)&sB[0][(r0l + 64) * SK + kql] =
            make_uint4(f2tf(b1.x), f2tf(b1.y), f2tf(b1.z), f2tf(b1.w));
    }

    const int NIT = HID_ / 16;
    for (int it = 0; it < NIT; it++) {
        __syncthreads();
        const int cur = it & 1;

        float4 a0, a1, b0, b1;
        const bool more = (it + 1) < NIT;
        if (more) {
            const int kk = (it + 1) * 16;
            a0 = *(const float4*)(Qb + (size_t)(m0 + r0l) * HID_ + kk + kql);
            a1 = *(const float4*)(Qb + (size_t)(m0 + r0l + 64) * HID_ + kk + kql);
            b0 = *(const float4*)(Kb + (size_t)(n0 + r0l) * HID_ + kk + kql);
            b1 = *(const float4*)(Kb + (size_t)(n0 + r0l + 64) * HID_ + kk + kql);
        }

#pragma unroll
        for (int ks = 0; ks < 16; ks += 8) {
            unsigned af[4][4];
#pragma unroll
            for (int mt = 0; mt < 4; mt++) {
                const int r = wm + mt * 16 + qid;
                af[mt][0] = sA[cur][r * SK + ks + rid];
                af[mt][1] = sA[cur][(r + 8) * SK + ks + rid];
                af[mt][2] = sA[cur][r * SK + ks + 4 + rid];
                af[mt][3] = sA[cur][(r + 8) * SK + ks + 4 + rid];
            }
            unsigned bf[4][2];
#pragma unroll
            for (int nt = 0; nt < 4; nt++) {
                const int c = wn + nt * 8 + qid;
                bf[nt][0] = sB[cur][c * SK + ks + rid];
                bf[nt][1] = sB[cur][c * SK + ks + 4 + rid];
            }
#pragma unroll
            for (int mt = 0; mt < 4; mt++)
#pragma unroll
                for (int nt = 0; nt < 4; nt++)
                    mma_tf32(acc[mt][nt], af[mt], bf[nt]);
        }

        if (more) {
            const int nxt = cur ^ 1;
            *(uint4*)&sA[nxt][r0l * SK + kql] =
                make_uint4(f2tf(a0.x), f2tf(a0.y), f2tf(a0.z), f2tf(a0.w));
            *(uint4*)&sA[nxt][(r0l + 64) * SK + kql] =
                make_uint4(f2tf(a1.x), f2tf(a1.y), f2tf(a1.z), f2tf(a1.w));
            *(uint4*)&sB[nxt][r0l * SK + kql] =
                make_uint4(f2tf(b0.x), f2tf(b0.y), f2tf(b0.z), f2tf(b0.w));
            *(uint4*)&sB[nxt][(r0l + 64) * SK + kql] =
                make_uint4(f2tf(b1.x), f2tf(b1.y), f2tf(b1.z), f2tf(b1.w));
        }
    }

    // epilogue: scale, mask-multiply, exp, store
    const float s = 0.03125f;
#pragma unroll
    for (int mt = 0; mt < 4; mt++) {
#pragma unroll
        for (int nt = 0; nt < 4; nt++) {
            const int r = m0 + wm + mt * 16 + qid;
            const int c = n0 + wn + nt * 8 + 2 * rid;
            const size_t i0 = ((size_t)b * LQ_ + r) * LK_ + c;
            const size_t i1 = ((size_t)b * LQ_ + r + 8) * LK_ + c;
            float2 ma = *(const float2*)(mask + i0);
            float2 mb = *(const float2*)(mask + i1);
            float2 o0, o1;
            o0.x = expf(acc[mt][nt][0] * s * ma.x);
            o0.y = expf(acc[mt][nt][1] * s * ma.y);
            o1.x = expf(acc[mt][nt][2] * s * mb.x);
            o1.y = expf(acc[mt][nt][3] * s * mb.y);
            *(float2*)(P + i0) = o0;
            *(float2*)(P + i1) = o1;
        }
    }
}

// ---------------------------------------------------------------------------
// Kernel 2: per-row normalization (unchanged from baseline)
// ---------------------------------------------------------------------------
__global__ __launch_bounds__(256)
void k2_norm(float* __restrict__ P)
{
    __shared__ float red[256];
    float* prow = P + (size_t)blockIdx.x * LK_;
    const int tid = threadIdx.x;

    float4 v0 = ((const float4*)prow)[tid];
    float4 v1 = ((const float4*)prow)[tid + 256];
    float s = v0.x + v0.y + v0.z + v0.w + v1.x + v1.y + v1.z + v1.w;
    red[tid] = s;
    __syncthreads();
#pragma unroll
    for (int off = 128; off > 0; off >>= 1) {
        if (tid < off) red[tid] += red[tid + off];
        __syncthreads();
    }
    const float inv = 1.0f / red[0];
    v0.x *= inv; v0.y *= inv; v0.z *= inv; v0.w *= inv;
    v1.x *= inv; v1.y *= inv; v1.z *= inv; v1.w *= inv;
    ((float4*)prow)[tid]       = v0;
    ((float4*)prow)[tid + 256] = v1;
}

// ---------------------------------------------------------------------------
// Kernel 3: context = attn . K   (attn k-contiguous, K d-contiguous)
// Same MMA skeleton; B tile stored [k][n] with stride 136.
// ---------------------------------------------------------------------------
__global__ __launch_bounds__(256, 2)
void k3_av(const float* __restrict__ A, const float* __restrict__ Kf,
           float* __restrict__ C)
{
    __shared__ unsigned sA[2][128 * SK];
    __shared__ unsigned sB[2][16 * SN];

    const int b  = blockIdx.z;
    const int m0 = blockIdx.y * 128;
    const int n0 = blockIdx.x * 128;

    const float* Ab = A  + (size_t)b * LQ_ * LK_;
    const float* Kb = Kf + (size_t)b * LK_ * HID_;

    const int tid  = threadIdx.x;
    const int wid  = tid >> 5;
    const int lane = tid & 31;
    const int qid  = lane >> 2;
    const int rid  = lane & 3;
    const int wm   = (wid >> 2) * 64;
    const int wn   = (wid & 3) * 32;

    // A loader: (row, kq) like k1; B loader: (krow 0..15, nc step 4)
    const int r0l = tid >> 2;
    const int kql = (tid & 3) << 2;
    const int krl = tid >> 5;          // 0..7  (two passes -> 0..15)
    const int ncl = (tid & 31) << 2;   // 0..124

    float acc[4][4][4];
#pragma unroll
    for (int i = 0; i < 4; i++)
#pragma unroll
        for (int j = 0; j < 4; j++)
#pragma unroll
            for (int c = 0; c < 4; c++) acc[i][j][c] = 0.0f;

    {
        float4 a0 = *(const float4*)(Ab + (size_t)(m0 + r0l) * LK_ + kql);
        float4 a1 = *(const float4*)(Ab + (size_t)(m0 + r0l + 64) * LK_ + kql);
        float4 b0 = *(const float4*)(Kb + (size_t)krl * HID_ + n0 + ncl);
        float4 b1 = *(const float4*)(Kb + (size_t)(krl + 8) * HID_ + n0 + ncl);
        *(uint4*)&sA[0][r0l * SK + kql] =
            make_uint4(f2tf(a0.x), f2tf(a0.y), f2tf(a0.z), f2tf(a0.w));
        *(uint4*)&sA[0][(r0l + 64) * SK + kql] =
            make_uint4(f2tf(a1.x), f2tf(a1.y), f2tf(a1.z), f2tf(a1.w));
        *(uint4*)&sB[0][krl * SN + ncl] =
            make_uint4(f2tf(b0.x), f2tf(b0.y), f2tf(b0.z), f2tf(b0.w));
        *(uint4*)&sB[0][(krl + 8) * SN + ncl] =
            make_uint4(f2tf(b1.x), f2tf(b1.y), f2tf(b1.z), f2tf(b1.w));
    }

    const int NIT = LK_ / 16;
    for (int it = 0; it < NIT; it++) {
        __syncthreads();
        const int cur = it & 1;

        float4 a0, a1, b0, b1;
        const bool more = (it + 1) < NIT;
        if (more) {
            const int kk = (it + 1) * 16;
            a0 = *(const float4*)(Ab + (size_t)(m0 + r0l) * LK_ + kk + kql);
            a1 = *(const float4*)(Ab + (size_t)(m0 + r0l + 64) * LK_ + kk + kql);
            b0 = *(const float4*)(Kb + (size_t)(kk + krl) * HID_ + n0 + ncl);
            b1 = *(const float4*)(Kb + (size_t)(kk + krl + 8) * HID_ + n0 + ncl);
        }

#pragma unroll
        for (int ks = 0; ks < 16; ks += 8) {
            unsigned af[4][4];
#pragma unroll
            for (int mt = 0; mt < 4; mt++) {
                const int r = wm + mt * 16 + qid;
                af[mt][0] = sA[cur][r * SK + ks + rid];
                af[mt][1] = sA[cur][(r + 8) * SK + ks + rid];
                af[mt][2] = sA[cur][r * SK + ks + 4 + rid];
                af[mt][3] = sA[cur][(r + 8) * SK + ks + 4 + rid];
            }
            unsigned bf[4][2];
#pragma unroll
            for (int nt = 0; nt < 4; nt++) {
                const int c = wn + nt * 8 + qid;
                bf[nt][0] = sB[cur][(ks + rid) * SN + c];
                bf[nt][1] = sB[cur][(ks + 4 + rid) * SN + c];
            }
#pragma unroll
            for (int mt = 0; mt < 4; mt++)
#pragma unroll
                for (int nt = 0; nt < 4; nt++)
                    mma_tf32(acc[mt][nt], af[mt], bf[nt]);
        }

        if (more) {
            const int nxt = cur ^ 1;
            *(uint4*)&sA[nxt][r0l * SK + kql] =
                make_uint4(f2tf(a0.x), f2tf(a0.y), f2tf(a0.z), f2tf(a0.w));
            *(uint4*)&sA[nxt][(r0l + 64) * SK + kql] =
                make_uint4(f2tf(a1.x), f2tf(a1.y), f2tf(a1.z), f2tf(a1.w));
            *(uint4*)&sB[nxt][krl * SN + ncl] =
                make_uint4(f2tf(b0.x), f2tf(b0.y), f2tf(b0.z), f2tf(b0.w));
            *(uint4*)&sB[nxt][(krl + 8) * SN + ncl] =
                make_uint4(f2tf(b1.x), f2tf(b1.y), f2tf(b1.z), f2tf(b1.w));
        }
    }

#pragma unroll
    for (int mt = 0; mt < 4; mt++) {
#pragma unroll
        for (int nt = 0; nt < 4; nt++) {
            const int r = m0 + wm + mt * 16 + qid;
            const int c = n0 + wn + nt * 8 + 2 * rid;
            const size_t i0 = ((size_t)b * LQ_ + r) * HID_ + c;
            const size_t i1 = ((size_t)b * LQ_ + r + 8) * HID_ + c;
            *(float2*)(C + i0) = make_float2(acc[mt][nt][0], acc[mt][nt][1]);
            *(float2*)(C + i1) = make_float2(acc[mt][nt][2], acc[mt][nt][3]);
        }
    }
}

// ---------------------------------------------------------------------------
extern "C" void kernel_launch(void* const* d_in, const int* in_sizes, int n_in,
                              void* d_out, int out_size)
{
    const float* Q    = (const float*)d_in[0];
    const float* Kf   = (const float*)d_in[1];
    const float* mask = (const float*)d_in[2];

    float* ctx  = (float*)d_out;                      // [B, LQ, HID]
    float* attn = ctx + (size_t)B_ * LQ_ * HID_;      // [B, LQ, LK]

    dim3 g1(LK_ / 128, LQ_ / 128, B_);
    k1_qk_exp<<<g1, 256>>>(Q, Kf, mask, attn);

    k2_norm<<<B_ * LQ_, 256>>>(attn);

    dim3 g3(HID_ / 128, LQ_ / 128, B_);
    k3_av<<<g3, 256>>>(attn, Kf, ctx);
}